// round 9
// baseline (speedup 1.0000x reference)
#include <cuda_runtime.h>
#include <cuda_fp16.h>
#include <cstdint>
#include <math.h>

// Problem dims
#define N_B   32
#define T_B   243
#define V_B   17
#define NT_B  (N_B * T_B)          // 7776
#define MROWS (NT_B * V_B)         // 132192

// ---------------- scratch (static device memory; no allocations) ----------
__device__ __half g_xc [67682304];   // M*512  concat (xm_out | xa_out)
__device__ __half g_qkv[50761728];   // M*384
__device__ __half g_o  [16920576];   // M*128
__device__ __half g_h  [135364608];  // M*1024
__device__ __half h_xa [16920576];   // M*128  normalized attn input
__device__ __half h_xn [67682304];   // M*512  normalized MLP input
__device__ __half h_in_w [49152];
__device__ __half h_out_w[16384];
__device__ __half h_cm_w1[524288];
__device__ __half h_cm_w2[524288];

// ---------------- helpers -------------------------------------------------
__device__ __forceinline__ float gelu_f(float v) {
    return 0.5f * v * (1.0f + erff(v * 0.7071067811865475f));
}
__device__ __forceinline__ uint32_t smaddr(const void* p) {
    return (uint32_t)__cvta_generic_to_shared(p);
}
__device__ __forceinline__ void ldsm4(uint32_t* r, uint32_t a) {
    asm volatile("ldmatrix.sync.aligned.m8n8.x4.shared.b16 {%0,%1,%2,%3}, [%4];"
        : "=r"(r[0]), "=r"(r[1]), "=r"(r[2]), "=r"(r[3]) : "r"(a));
}
__device__ __forceinline__ void hmma(float* d, const uint32_t* a, const uint32_t* b) {
    asm volatile(
        "mma.sync.aligned.m16n8k16.row.col.f32.f16.f16.f32 "
        "{%0,%1,%2,%3},{%4,%5,%6,%7},{%8,%9},{%0,%1,%2,%3};"
        : "+f"(d[0]), "+f"(d[1]), "+f"(d[2]), "+f"(d[3])
        : "r"(a[0]), "r"(a[1]), "r"(a[2]), "r"(a[3]), "r"(b[0]), "r"(b[1]));
}
__device__ __forceinline__ void cp16(uint32_t dst, const void* src, bool pred) {
    int sz = pred ? 16 : 0;
    asm volatile("cp.async.cg.shared.global [%0], [%1], 16, %2;\n"
        :: "r"(dst), "l"(src), "r"(sz));
}
__device__ __forceinline__ void cp_commit() {
    asm volatile("cp.async.commit_group;\n" ::: "memory");
}
template <int NN>
__device__ __forceinline__ void cp_wait() {
    asm volatile("cp.async.wait_group %0;\n" :: "n"(NN) : "memory");
}

// ---------------- fp16 GEMM: out = act(A * W^T + bias) --------------------
// A: M x K fp16 (lda), W: N x K fp16. CTA tile 128x128, K-tile 64 (one SW128
// atom per row), 3-stage cp.async pipeline, ONE barrier per K-tile.
// MODE: 0 = bias, 1 = bias+gelu, 2 = bias+residual(fp32 x, stride 512)
#define GEMM_SMEM (3 * 32768 + 128)

template <int MODE, typename OT>
__device__ __forceinline__ void gemm_core(
    const __half* __restrict__ A, int lda,
    const __half* __restrict__ W, int K,
    const float* __restrict__ bias,
    const float* __restrict__ residual,
    OT* __restrict__ out, int ldc, int coff,
    int M)
{
    extern __shared__ char dynsmem[];
    const uint32_t sb = (smaddr(dynsmem) + 127u) & ~127u;

    const int tid  = threadIdx.x;
    const int lane = tid & 31;
    const int warp = tid >> 5;
    const int wm   = (warp & 1) * 64;
    const int wn   = (warp >> 1) * 32;
    const int n0   = blockIdx.x * 128;   // N fastest -> A-tile L2 reuse
    const int m0   = blockIdx.y * 128;

    uint32_t stA[3], stB[3];
#pragma unroll
    for (int s = 0; s < 3; s++) { stA[s] = sb + s * 32768; stB[s] = stA[s] + 16384; }

    float acc[4][4][4] = {};

    // stage: 128 rows x 64 halfs (128B rows), XOR-swizzled
    auto stage_load = [&](int s, int kk) {
#pragma unroll
        for (int i = 0; i < 4; i++) {
            int ch  = tid + i * 256;              // 0..1023
            int r   = ch >> 3, c16 = ch & 7;
            uint32_t swo = (uint32_t)(r * 128 + c16 * 16) ^ (uint32_t)((r & 7) << 4);
            cp16(stA[s] + swo, A + (size_t)(m0 + r) * lda + kk + c16 * 8, (m0 + r) < M);
            cp16(stB[s] + swo, W + (size_t)(n0 + r) * K + kk + c16 * 8, true);
        }
    };

    auto compute = [&](int s) {
#pragma unroll
        for (int ks = 0; ks < 4; ks++) {
            const int c = ks * 16 + 8 * (lane >> 4);
            uint32_t a[4][4], b[2][4];
#pragma unroll
            for (int mt = 0; mt < 4; mt++) {
                int r = wm + mt * 16 + (lane & 15);
                ldsm4(a[mt], stA[s] + ((uint32_t)(r * 128 + c * 2) ^ (uint32_t)((r & 7) << 4)));
            }
#pragma unroll
            for (int np = 0; np < 2; np++) {
                int r = wn + np * 16 + (lane & 15);
                ldsm4(b[np], stB[s] + ((uint32_t)(r * 128 + c * 2) ^ (uint32_t)((r & 7) << 4)));
            }
#pragma unroll
            for (int mt = 0; mt < 4; mt++)
#pragma unroll
                for (int nt = 0; nt < 4; nt++) {
                    uint32_t bb[2] = { b[nt >> 1][nt & 1], b[nt >> 1][(nt & 1) + 2] };
                    hmma(acc[mt][nt], a[mt], bb);
                }
        }
    };

    const int nT = K >> 6;
    int fetch = 0;
#pragma unroll
    for (int s = 0; s < 2; s++) {
        if (fetch < nT) stage_load(fetch, fetch << 6);
        cp_commit();
        fetch++;
    }
    for (int t = 0; t < nT; t++) {
        cp_wait<1>();
        __syncthreads();
        compute(t % 3);
        if (fetch < nT) stage_load(fetch % 3, fetch << 6);
        cp_commit();
        fetch++;
    }

    // epilogue
    const int er = lane >> 2;
    const int ec = (lane & 3) * 2;
#pragma unroll
    for (int mt = 0; mt < 4; mt++) {
#pragma unroll
        for (int hh = 0; hh < 2; hh++) {
            int row = m0 + wm + mt * 16 + er + hh * 8;
            if (row >= M) continue;
#pragma unroll
            for (int nt = 0; nt < 4; nt++) {
                int col  = wn + nt * 8 + ec;
                int gcol = n0 + col;
                float v0 = acc[mt][nt][hh * 2 + 0] + bias[gcol];
                float v1 = acc[mt][nt][hh * 2 + 1] + bias[gcol + 1];
                if (MODE == 1) { v0 = gelu_f(v0); v1 = gelu_f(v1); }
                if (MODE == 2) {
                    const float* rp = residual + (size_t)row * 512 + coff + gcol;
                    v0 += rp[0]; v1 += rp[1];
                }
                if constexpr (sizeof(OT) == 2) {
                    *(__half2*)(out + (size_t)row * ldc + coff + gcol) =
                        __floats2half2_rn(v0, v1);
                } else {
                    *(float2*)(out + (size_t)row * ldc + coff + gcol) =
                        make_float2(v0, v1);
                }
            }
        }
    }
}

// ---------------- GEMM wrappers ------------------------------------------
__global__ __launch_bounds__(256, 2) void k_gemm_qkv(const float* __restrict__ in_b) {
    gemm_core<0, __half>(h_xa, 128, h_in_w, 128, in_b, nullptr,
                         g_qkv, 384, 0, MROWS);
}
__global__ __launch_bounds__(256, 2) void k_gemm_proj(const float* __restrict__ out_b) {
    gemm_core<0, __half>(g_o, 128, h_out_w, 128, out_b, nullptr,
                         g_xc, 512, 384, MROWS);
}
__global__ __launch_bounds__(256, 2) void k_gemm_mlp1(const float* __restrict__ cm_b1) {
    gemm_core<1, __half>(h_xn, 512, h_cm_w1, 512, cm_b1, nullptr,
                         g_h, 1024, 0, MROWS);
}
__global__ __launch_bounds__(256, 2) void k_gemm_mlp2(
    const float* __restrict__ cm_b2, const float* __restrict__ x,
    float* __restrict__ out)
{
    gemm_core<2, float>(g_h, 1024, h_cm_w2, 1024, cm_b2, x,
                        out, 512, 0, MROWS);
}

// ---------------- weight conversion fp32 -> fp16 --------------------------
__global__ __launch_bounds__(256) void k_cvt_w(
    const float* __restrict__ in_w, const float* __restrict__ out_w,
    const float* __restrict__ cm_w1, const float* __restrict__ cm_w2)
{
    int i = blockIdx.x * 256 + threadIdx.x;
    if (i < 49152) h_in_w[i] = __float2half(in_w[i]);
    if (i < 16384) h_out_w[i] = __float2half(out_w[i]);
    if (i < 524288) {
        h_cm_w1[i] = __float2half(cm_w1[i]);
        h_cm_w2[i] = __float2half(cm_w2[i]);
    }
}

// ---------------- token mixer (mix over V=17, channels d<384) -------------
__global__ __launch_bounds__(384) void k_tokenmix(
    const float* __restrict__ x,
    const float* __restrict__ w1, const float* __restrict__ b1,
    const float* __restrict__ w2, const float* __restrict__ b2)
{
    __shared__ float sw1[289], sw2[289], sb1[17], sb2[17];
    int tid = threadIdx.x;
    if (tid < 289) { sw1[tid] = w1[tid]; sw2[tid] = w2[tid]; }
    if (tid < 17)  { sb1[tid] = b1[tid]; sb2[tid] = b2[tid]; }
    __syncthreads();

    size_t base = (size_t)blockIdx.x * V_B * 512;
    int d = tid;  // 0..383
    float xv[17];
#pragma unroll
    for (int v = 0; v < 17; v++) xv[v] = x[base + (size_t)v * 512 + d];
    float h[17];
#pragma unroll
    for (int u = 0; u < 17; u++) {
        float s = sb1[u];
#pragma unroll
        for (int v = 0; v < 17; v++) s += sw1[u * 17 + v] * xv[v];
        h[u] = gelu_f(s);
    }
#pragma unroll
    for (int u = 0; u < 17; u++) {
        float s = sb2[u];
#pragma unroll
        for (int v = 0; v < 17; v++) s += sw2[u * 17 + v] * h[v];
        g_xc[base + (size_t)u * 512 + d] = __float2half(s);
    }
}

// ---------------- RMSNorm prep: write normalized fp16 A -------------------
__global__ __launch_bounds__(256) void k_prep_a(
    const float* __restrict__ x, const float* __restrict__ na_w)
{
    int row = blockIdx.x * 8 + (threadIdx.x >> 5);
    if (row >= MROWS) return;
    int lane = threadIdx.x & 31;
    const float* p = x + (size_t)row * 512 + 384;
    float4 v = *(const float4*)(p + lane * 4);
    float ss = v.x * v.x + v.y * v.y + v.z * v.z + v.w * v.w;
#pragma unroll
    for (int s = 16; s; s >>= 1) ss += __shfl_xor_sync(0xffffffffu, ss, s);
    float r = rsqrtf(ss * (1.0f / 128.0f) + 1e-6f);
    float4 w = *(const float4*)(na_w + lane * 4);
    __half2* o = (__half2*)(h_xa + (size_t)row * 128 + lane * 4);
    o[0] = __floats2half2_rn(v.x * r * w.x, v.y * r * w.y);
    o[1] = __floats2half2_rn(v.z * r * w.z, v.w * r * w.w);
}

__global__ __launch_bounds__(256) void k_prep_f(const float* __restrict__ nf_w) {
    int row = blockIdx.x * 8 + (threadIdx.x >> 5);
    if (row >= MROWS) return;
    int lane = threadIdx.x & 31;
    const __half* p = g_xc + (size_t)row * 512;
    float vals[16];
    float ss = 0.f;
#pragma unroll
    for (int c = 0; c < 2; c++) {
        uint4 u = *(const uint4*)(p + lane * 8 + c * 256);
        __half2* h = (__half2*)&u;
#pragma unroll
        for (int j = 0; j < 4; j++) {
            float2 f = __half22float2(h[j]);
            vals[c * 8 + j * 2] = f.x; vals[c * 8 + j * 2 + 1] = f.y;
            ss += f.x * f.x + f.y * f.y;
        }
    }
#pragma unroll
    for (int s = 16; s; s >>= 1) ss += __shfl_xor_sync(0xffffffffu, ss, s);
    float r = rsqrtf(ss * (1.0f / 512.0f) + 1e-6f);
    __half* o = h_xn + (size_t)row * 512;
#pragma unroll
    for (int c = 0; c < 2; c++) {
        int base = lane * 8 + c * 256;
        __half2 hh[4];
#pragma unroll
        for (int j = 0; j < 4; j++) {
            float w0 = nf_w[base + j * 2], w1 = nf_w[base + j * 2 + 1];
            hh[j] = __floats2half2_rn(vals[c * 8 + j * 2] * r * w0,
                                      vals[c * 8 + j * 2 + 1] * r * w1);
        }
        *(uint4*)(o + base) = *(uint4*)hh;
    }
}

// ---------------- attention (one block per (n,t); 17x17 per head) ---------
__global__ __launch_bounds__(96) void k_attn() {
    __shared__ __align__(16) float s[17 * 384];
    int b = blockIdx.x;
    const uint4* g4 = (const uint4*)(g_qkv + (size_t)b * 17 * 384);
    for (int i = threadIdx.x; i < 17 * 48; i += 96) {
        uint4 u = g4[i];
        __half2* h = (__half2*)&u;
        float* dst = &s[i * 8];
#pragma unroll
        for (int j = 0; j < 4; j++) {
            float2 f = __half22float2(h[j]);
            dst[j * 2] = f.x; dst[j * 2 + 1] = f.y;
        }
    }
    __syncthreads();

    int tid = threadIdx.x;
    if (tid < 68) {
        int q  = tid % 17;
        int hh = tid / 17;
        float qv[32];
#pragma unroll
        for (int i = 0; i < 8; i++) {
            float4 v = *(const float4*)&s[q * 384 + hh * 32 + i * 4];
            qv[i * 4] = v.x; qv[i * 4 + 1] = v.y; qv[i * 4 + 2] = v.z; qv[i * 4 + 3] = v.w;
        }
        float sc[17];
        float mx = -1e30f;
#pragma unroll
        for (int j = 0; j < 17; j++) {
            const float* kp = &s[j * 384 + 128 + hh * 32];
            float a = 0.f;
#pragma unroll
            for (int i = 0; i < 8; i++) {
                float4 v = *(const float4*)(kp + i * 4);
                a += qv[i * 4] * v.x + qv[i * 4 + 1] * v.y +
                     qv[i * 4 + 2] * v.z + qv[i * 4 + 3] * v.w;
            }
            a *= 0.17677669529663687f;
            sc[j] = a;
            mx = fmaxf(mx, a);
        }
        float sum = 0.f;
#pragma unroll
        for (int j = 0; j < 17; j++) { sc[j] = __expf(sc[j] - mx); sum += sc[j]; }
        float inv = 1.f / sum;
        float ov[32];
#pragma unroll
        for (int i = 0; i < 32; i++) ov[i] = 0.f;
#pragma unroll
        for (int j = 0; j < 17; j++) {
            float p = sc[j] * inv;
            const float* vp = &s[j * 384 + 256 + hh * 32];
#pragma unroll
            for (int i = 0; i < 8; i++) {
                float4 v = *(const float4*)(vp + i * 4);
                ov[i * 4]     += p * v.x;
                ov[i * 4 + 1] += p * v.y;
                ov[i * 4 + 2] += p * v.z;
                ov[i * 4 + 3] += p * v.w;
            }
        }
        __half* op = g_o + ((size_t)b * 17 + q) * 128 + hh * 32;
#pragma unroll
        for (int i = 0; i < 8; i++)
            *(__half2*)(op + i * 4) = __floats2half2_rn(ov[i * 4], ov[i * 4 + 1]),
            *(__half2*)(op + i * 4 + 2) = __floats2half2_rn(ov[i * 4 + 2], ov[i * 4 + 3]);
    }
}

// ---------------- launch --------------------------------------------------
extern "C" void kernel_launch(void* const* d_in, const int* in_sizes, int n_in,
                              void* d_out, int out_size)
{
    const float* x     = (const float*)d_in[0];
    const float* tm_w1 = (const float*)d_in[1];
    const float* tm_b1 = (const float*)d_in[2];
    const float* tm_w2 = (const float*)d_in[3];
    const float* tm_b2 = (const float*)d_in[4];
    const float* na_w  = (const float*)d_in[5];
    const float* in_w  = (const float*)d_in[6];
    const float* in_b  = (const float*)d_in[7];
    const float* out_w = (const float*)d_in[8];
    const float* out_b = (const float*)d_in[9];
    const float* nf_w  = (const float*)d_in[10];
    const float* cm_w1 = (const float*)d_in[11];
    const float* cm_b1 = (const float*)d_in[12];
    const float* cm_w2 = (const float*)d_in[13];
    const float* cm_b2 = (const float*)d_in[14];
    float* out = (float*)d_out;

    const int mt = (MROWS + 127) / 128;  // 1033 M-tiles

    static int attr_done = 0;
    if (!attr_done) {
        cudaFuncSetAttribute(k_gemm_qkv,  cudaFuncAttributeMaxDynamicSharedMemorySize, GEMM_SMEM);
        cudaFuncSetAttribute(k_gemm_proj, cudaFuncAttributeMaxDynamicSharedMemorySize, GEMM_SMEM);
        cudaFuncSetAttribute(k_gemm_mlp1, cudaFuncAttributeMaxDynamicSharedMemorySize, GEMM_SMEM);
        cudaFuncSetAttribute(k_gemm_mlp2, cudaFuncAttributeMaxDynamicSharedMemorySize, GEMM_SMEM);
        attr_done = 1;
    }

    k_cvt_w<<<2048, 256>>>(in_w, out_w, cm_w1, cm_w2);
    k_tokenmix<<<NT_B, 384>>>(x, tm_w1, tm_b1, tm_w2, tm_b2);
    k_prep_a<<<(MROWS + 7) / 8, 256>>>(x, na_w);
    k_gemm_qkv<<<dim3(3, mt), 256, GEMM_SMEM>>>(in_b);
    k_attn<<<NT_B, 96>>>();
    k_gemm_proj<<<dim3(1, mt), 256, GEMM_SMEM>>>(out_b);
    k_prep_f<<<(MROWS + 7) / 8, 256>>>(nf_w);
    k_gemm_mlp1<<<dim3(8, mt), 256, GEMM_SMEM>>>(cm_b1);
    k_gemm_mlp2<<<dim3(4, mt), 256, GEMM_SMEM>>>(cm_b2, x, out);
}